// round 2
// baseline (speedup 1.0000x reference)
#include <cuda_runtime.h>
#include <cuda_bf16.h>

#define Bb 128
#define Tt 256
#define Dd 1024
#define Hh 1024
#define Vv 1024
#define Ss 128
#define H3 3072
#define NBLK 148

// ---------------- scratch (device globals; no cudaMalloc allowed) -----------
__device__ __align__(16) float g_wh[(long)Bb * Tt * Hh];     // 134 MB
__device__ __align__(16) float g_part_proj[8 * Bb * Hh];
__device__ __align__(16) float g_part_gi[2 * Bb * H3];
__device__ __align__(16) float g_part_gh[Bb * H3];
__device__ __align__(16) float g_part_pre[8 * Bb * Vv];
__device__ __align__(16) float g_xcat[Bb * 2048];            // [c | y]
__device__ __align__(16) float g_xr[Bb * 2048];              // [c | s_new]
__device__ __align__(16) float g_s[Bb * Hh];

// barrier state
__device__ unsigned g_bar_count = 0;
__device__ unsigned g_bar_gen = 0;

// ---------------- MUFU-based math -------------------------------------------
__device__ __forceinline__ float ex2_approx(float x) {
    float r;
    asm("ex2.approx.ftz.f32 %0, %1;" : "=f"(r) : "f"(x));
    return r;
}
__device__ __forceinline__ float rcp_approx(float x) {
    float r;
    asm("rcp.approx.ftz.f32 %0, %1;" : "=f"(r) : "f"(x));
    return r;
}
__device__ __forceinline__ float exp_mufu(float x) {
    return ex2_approx(x * 1.4426950408889634f);
}
// tanh(x) = sign(x) * (1 - 2e/(1+e)), e = exp(-2|x|)
__device__ __forceinline__ float tanh_mufu(float x) {
    float ax = fabsf(x);
    float e  = ex2_approx(ax * -2.885390081777927f);   // e^{-2ax}
    float r  = rcp_approx(1.0f + e);
    float th = fmaf(-2.0f * e, r, 1.0f);
    return copysignf(th, x);
}
__device__ __forceinline__ float sigmoid_mufu(float x) {
    float e = ex2_approx(x * -1.4426950408889634f);    // e^{-x}
    return rcp_approx(1.0f + e);
}

__device__ __forceinline__ float warp_sum(float v) {
#pragma unroll
    for (int o = 16; o > 0; o >>= 1) v += __shfl_xor_sync(0xffffffffu, v, o);
    return v;
}
__device__ __forceinline__ float warp_max(float v) {
#pragma unroll
    for (int o = 16; o > 0; o >>= 1) v = fmaxf(v, __shfl_xor_sync(0xffffffffu, v, o));
    return v;
}

// ---------------- grid barrier ----------------------------------------------
__device__ __forceinline__ void grid_barrier() {
    __syncthreads();
    if (threadIdx.x == 0) {
        volatile unsigned* genp = &g_bar_gen;
        unsigned gen = *genp;                // exact current gen (monotonic L2)
        __threadfence();                     // my writes -> L2; also CCTL.IVALL
        unsigned arrived = atomicAdd(&g_bar_count, 1u);
        if (arrived == (unsigned)(gridDim.x - 1)) {
            *(volatile unsigned*)&g_bar_count = 0u;
            __threadfence();
            atomicExch(&g_bar_gen, gen + 1u);
        } else {
            while (*genp == gen) { }
        }
        __threadfence();                     // invalidate L1 before consuming
    }
    __syncthreads();
}

// ---------------- 128x64 tile GEMM (device fn, split-K partial) --------------
// C[m, n] (+)= sum_k A[m, k] * Bw[n, k], m in [0,128), n tile of 64.
// A points at (m=0, k0); Bw points at (n0, k0); C points at (0, n0).
__device__ __forceinline__ void gemm_tile(
    const float* A, int lda,
    const float* Bw, int ldb,
    int kcount,
    float* C, int ldc,
    float (&As)[16][132], float (&Bs)[16][68])
{
    const int tid = threadIdx.x;
    const int tx = tid & 15;
    const int ty = tid >> 4;
    float acc[8][4];
#pragma unroll
    for (int i = 0; i < 8; i++)
#pragma unroll
        for (int j = 0; j < 4; j++) acc[i][j] = 0.0f;

    for (int kt = 0; kt < kcount; kt += 16) {
#pragma unroll
        for (int i = 0; i < 2; i++) {
            int v = tid * 2 + i;              // 0..511
            int m = v >> 2;
            int kq = (v & 3) << 2;
            float4 a4 = *(const float4*)(A + (long)m * lda + kt + kq);
            As[kq + 0][m] = a4.x; As[kq + 1][m] = a4.y;
            As[kq + 2][m] = a4.z; As[kq + 3][m] = a4.w;
        }
        {
            int n = tid >> 2;
            int kq = (tid & 3) << 2;
            float4 b4 = *(const float4*)(Bw + (long)n * ldb + kt + kq);
            Bs[kq + 0][n] = b4.x; Bs[kq + 1][n] = b4.y;
            Bs[kq + 2][n] = b4.z; Bs[kq + 3][n] = b4.w;
        }
        __syncthreads();
#pragma unroll
        for (int k = 0; k < 16; k++) {
            float a[8], b[4];
            *(float4*)&a[0] = *(const float4*)&As[k][ty * 8];
            *(float4*)&a[4] = *(const float4*)&As[k][ty * 8 + 4];
            *(float4*)&b[0] = *(const float4*)&Bs[k][tx * 4];
#pragma unroll
            for (int i = 0; i < 8; i++)
#pragma unroll
                for (int j = 0; j < 4; j++)
                    acc[i][j] = fmaf(a[i], b[j], acc[i][j]);
        }
        __syncthreads();
    }
#pragma unroll
    for (int i = 0; i < 8; i++) {
        float4 o = make_float4(acc[i][0], acc[i][1], acc[i][2], acc[i][3]);
        *(float4*)(C + (long)(ty * 8 + i) * ldc + tx * 4) = o;
    }
}

// ---------------- standalone GEMM kernel (wh precompute / s0) ----------------
__global__ void __launch_bounds__(256)
gemm_part(const float* __restrict__ A, int lda,
          const float* __restrict__ Bw, int ldb,
          int N, int ksplit,
          float* __restrict__ Cp, int mtot)
{
    __shared__ __align__(16) float As[16][132];
    __shared__ __align__(16) float Bs[16][68];
    const int nb = blockIdx.x, mb = blockIdx.y, z = blockIdx.z;
    const int k0 = z * ksplit;
    gemm_tile(A + (long)(mb * 128) * lda + k0, lda,
              Bw + (long)(nb * 64) * ldb + k0, ldb,
              ksplit,
              Cp + ((long)z * mtot + mb * 128) * N + nb * 64, N,
              As, Bs);
}

// s0 = tanh(sum of 4 partial slots + bias); y0 = 0
__global__ void init_state_kernel(const float* __restrict__ bias)
{
    int idx = blockIdx.x * 256 + threadIdx.x;   // < 128*1024
    int b = idx >> 10, hh = idx & 1023;
    float v = bias[hh];
#pragma unroll
    for (int q = 0; q < 4; q++) v += g_part_proj[q * (Bb * Hh) + idx];
    g_s[idx] = tanh_mufu(v);
    g_xcat[b * 2048 + 1024 + hh] = 0.0f;        // y = 0
}

// ---------------- the persistent kernel --------------------------------------
__global__ void __launch_bounds__(256, 1)
persist_kernel(const float* __restrict__ h,
               const float* __restrict__ w_s_a, const float* __restrict__ b_s_a,
               const float* __restrict__ w_a,
               const float* __restrict__ gru_w_ih, const float* __restrict__ gru_w_hh,
               const float* __restrict__ gru_b_ih, const float* __restrict__ gru_b_hh,
               const float* __restrict__ rnn_w_ih, const float* __restrict__ rnn_w_hh,
               const float* __restrict__ rnn_b_ih, const float* __restrict__ rnn_b_hh,
               float* __restrict__ out)
{
    __shared__ __align__(16) float As[16][132];   // aliased by attn phases
    __shared__ __align__(16) float Bs[16][68];
    __shared__ float s_bc;

    const int blk = blockIdx.x;
    const int tid = threadIdx.x;
    const int w = tid >> 5, l = tid & 31;

    float* p_sh = &As[0][0];          // 1024 floats
    float* w_sh = p_sh + 1024;        // 1024 floats (As has 2112)
    float* sc   = &Bs[0][0];          // 256 floats
    float* red  = sc + 256;           // 8 floats   (Bs has 1088)

    for (int step = 0; step < Ss; step++) {
        // ---- Phase A: proj partials = s @ w_s_a^T (16 n-tiles x 8 k-splits)
        if (blk < 128) {
            int nt = blk & 15, z = blk >> 4;
            gemm_tile(g_s + z * 128, Hh,
                      w_s_a + (long)(nt * 64) * Hh + z * 128, Hh,
                      128,
                      g_part_proj + z * (Bb * Hh) + nt * 64, Hh,
                      As, Bs);
        }
        grid_barrier();

        // ---- Phase B: per-b attention (reduce proj, scores, softmax, ctx)
        if (blk < 128) {
            int b = blk;
            // reduce proj partials + bias into shared; stage w_a
            {
                float4 acc = ((const float4*)b_s_a)[tid];
#pragma unroll
                for (int z = 0; z < 8; z++) {
                    float4 v = ((const float4*)(g_part_proj + z * (Bb * Hh) + b * Hh))[tid];
                    acc.x += v.x; acc.y += v.y; acc.z += v.z; acc.w += v.w;
                }
                ((float4*)p_sh)[tid] = acc;
                ((float4*)w_sh)[tid] = ((const float4*)w_a)[tid];
            }
            __syncthreads();
            // scores: warp w handles t in [w*32, w*32+32)
            const float4* whb = (const float4*)(g_wh + (long)b * Tt * Hh);
            for (int tt = 0; tt < 32; tt++) {
                int t = w * 32 + tt;
                const float4* whp = whb + (long)t * 256;
                float acc = 0.0f;
#pragma unroll
                for (int jj = 0; jj < 8; jj++) {
                    int fi = jj * 32 + l;
                    float4 v  = whp[fi];
                    float4 p  = ((const float4*)p_sh)[fi];
                    float4 wa = ((const float4*)w_sh)[fi];
                    acc = fmaf(tanh_mufu(v.x + p.x), wa.x, acc);
                    acc = fmaf(tanh_mufu(v.y + p.y), wa.y, acc);
                    acc = fmaf(tanh_mufu(v.z + p.z), wa.z, acc);
                    acc = fmaf(tanh_mufu(v.w + p.w), wa.w, acc);
                }
                acc = warp_sum(acc);
                if (l == 0) sc[t] = acc;
            }
            __syncthreads();
            // softmax over sc[256]
            {
                float v = sc[tid];
                float m = warp_max(v);
                if (l == 0) red[w] = m;
                __syncthreads();
                if (tid == 0) {
                    float mm = red[0];
#pragma unroll
                    for (int i = 1; i < 8; i++) mm = fmaxf(mm, red[i]);
                    s_bc = mm;
                }
                __syncthreads();
                float e = exp_mufu(v - s_bc);
                float s = warp_sum(e);
                if (l == 0) red[w] = s;
                __syncthreads();
                if (tid == 0) {
                    float ss = 0.0f;
#pragma unroll
                    for (int i = 0; i < 8; i++) ss += red[i];
                    s_bc = rcp_approx(ss);
                }
                __syncthreads();
                sc[tid] = e * s_bc;
            }
            __syncthreads();
            // ctx: c = sum_t a[t] * h[b,t,:]
            {
                const float4* hp = (const float4*)(h + (long)b * Tt * Dd);
                float4 c = make_float4(0.f, 0.f, 0.f, 0.f);
#pragma unroll 4
                for (int t = 0; t < Tt; t++) {
                    float a = sc[t];
                    float4 v = hp[(long)t * 256 + tid];
                    c.x = fmaf(a, v.x, c.x); c.y = fmaf(a, v.y, c.y);
                    c.z = fmaf(a, v.z, c.z); c.w = fmaf(a, v.w, c.w);
                }
                ((float4*)(g_xcat + b * 2048))[tid] = c;
                ((float4*)(g_xr   + b * 2048))[tid] = c;
            }
        }
        grid_barrier();

        // ---- Phase C: gi = [c,y] @ gru_w_ih^T (48 tiles x 2 ksplits),
        //               gh = s @ gru_w_hh^T (48 tiles, full K)
        if (blk < 96) {
            int nt = blk >> 1, z = blk & 1;
            gemm_tile(g_xcat + z * 1024, 2048,
                      gru_w_ih + (long)(nt * 64) * 2048 + z * 1024, 2048,
                      1024,
                      g_part_gi + (long)z * (Bb * H3) + nt * 64, H3,
                      As, Bs);
        } else if (blk < 144) {
            int nt = blk - 96;
            gemm_tile(g_s, Hh,
                      gru_w_hh + (long)(nt * 64) * Hh, Hh,
                      1024,
                      g_part_gh + nt * 64, H3,
                      As, Bs);
        }
        grid_barrier();

        // ---- Phase D: GRU elementwise
        for (int idx = blk * 256 + tid; idx < Bb * Hh; idx += NBLK * 256) {
            int b = idx >> 10, hh = idx & 1023;
            float gir = gru_b_ih[hh], giz = gru_b_ih[1024 + hh], gin = gru_b_ih[2048 + hh];
#pragma unroll
            for (int q = 0; q < 2; q++) {
                const float* p = g_part_gi + (long)(q * Bb + b) * H3 + hh;
                gir += p[0]; giz += p[1024]; gin += p[2048];
            }
            const float* ph = g_part_gh + (long)b * H3 + hh;
            float ghr = gru_b_hh[hh] + ph[0];
            float ghz = gru_b_hh[1024 + hh] + ph[1024];
            float ghn = gru_b_hh[2048 + hh] + ph[2048];
            float r = sigmoid_mufu(gir + ghr);
            float z = sigmoid_mufu(giz + ghz);
            float n = tanh_mufu(fmaf(r, ghn, gin));
            float sv = g_s[idx];
            float sn = fmaf(z, sv - n, n);
            g_s[idx] = sn;
            g_xr[b * 2048 + 1024 + hh] = sn;
        }
        grid_barrier();

        // ---- Phase E: pre partials (ih: 16 tiles x 4 splits; hh: 16 x 4)
        if (blk < 64) {
            int nt = blk >> 2, z = blk & 3;
            gemm_tile(g_xr + z * 512, 2048,
                      rnn_w_ih + (long)(nt * 64) * 2048 + z * 512, 2048,
                      512,
                      g_part_pre + (long)z * (Bb * Vv) + nt * 64, Vv,
                      As, Bs);
        } else if (blk < 128) {
            int t2 = blk - 64;
            int nt = t2 >> 2, z = t2 & 3;
            gemm_tile(g_xcat + 1024 + z * 256, 2048,
                      rnn_w_hh + (long)(nt * 64) * Hh + z * 256, Hh,
                      256,
                      g_part_pre + (long)(4 + z) * (Bb * Vv) + nt * 64, Vv,
                      As, Bs);
        }
        grid_barrier();

        // ---- Phase F: out = softmax(tanh(pre)); store y and output
        if (blk < 128) {
            int b = blk;
            float4 acc = ((const float4*)rnn_b_ih)[tid];
            float4 b2  = ((const float4*)rnn_b_hh)[tid];
            acc.x += b2.x; acc.y += b2.y; acc.z += b2.z; acc.w += b2.w;
#pragma unroll
            for (int q = 0; q < 8; q++) {
                float4 p = ((const float4*)(g_part_pre + (long)q * (Bb * Vv) + b * Vv))[tid];
                acc.x += p.x; acc.y += p.y; acc.z += p.z; acc.w += p.w;
            }
            float t0 = tanh_mufu(acc.x), t1 = tanh_mufu(acc.y);
            float t2 = tanh_mufu(acc.z), t3 = tanh_mufu(acc.w);
            float m = fmaxf(fmaxf(t0, t1), fmaxf(t2, t3));
            m = warp_max(m);
            if (l == 0) red[w] = m;
            __syncthreads();
            if (tid == 0) {
                float mm = red[0];
#pragma unroll
                for (int i = 1; i < 8; i++) mm = fmaxf(mm, red[i]);
                s_bc = mm;
            }
            __syncthreads();
            float mx = s_bc;
            float e0 = exp_mufu(t0 - mx), e1 = exp_mufu(t1 - mx);
            float e2 = exp_mufu(t2 - mx), e3 = exp_mufu(t3 - mx);
            float s = warp_sum(e0 + e1 + e2 + e3);
            if (l == 0) red[w] = s;
            __syncthreads();
            if (tid == 0) {
                float ss = 0.0f;
#pragma unroll
                for (int i = 0; i < 8; i++) ss += red[i];
                s_bc = rcp_approx(ss);
            }
            __syncthreads();
            float inv = s_bc;
            float4 y = make_float4(e0 * inv, e1 * inv, e2 * inv, e3 * inv);
            ((float4*)(g_xcat + b * 2048 + 1024))[tid] = y;
            ((float4*)(out + ((long)b * Ss + step) * Vv))[tid] = y;
            __syncthreads();   // protect red/s_bc (shared) before next step reuse
        }
        // no barrier needed F -> next A (disjoint read/write sets; next
        // consumers of F's outputs are >=2 barriers away)
    }
}

// ---------------- launcher ----------------------------------------------------
extern "C" void kernel_launch(void* const* d_in, const int* in_sizes, int n_in,
                              void* d_out, int out_size)
{
    const float* h        = (const float*)d_in[0];
    const float* w_h_a    = (const float*)d_in[1];
    const float* w_s_a    = (const float*)d_in[2];
    const float* b_s_a    = (const float*)d_in[3];
    const float* w_a      = (const float*)d_in[4];
    const float* w_init_s = (const float*)d_in[5];
    const float* b_init_s = (const float*)d_in[6];
    const float* gru_w_ih = (const float*)d_in[7];
    const float* gru_w_hh = (const float*)d_in[8];
    const float* gru_b_ih = (const float*)d_in[9];
    const float* gru_b_hh = (const float*)d_in[10];
    const float* rnn_w_ih = (const float*)d_in[11];
    const float* rnn_w_hh = (const float*)d_in[12];
    const float* rnn_b_ih = (const float*)d_in[13];
    const float* rnn_b_hh = (const float*)d_in[14];
    float* out = (float*)d_out;

    float *wh, *pproj;
    cudaGetSymbolAddress((void**)&wh,    g_wh);
    cudaGetSymbolAddress((void**)&pproj, g_part_proj);

    // Node 1: wh = h @ w_h_a^T  (M = B*T = 32768, full K per block)
    gemm_part<<<dim3(16, 256, 1), 256>>>(h, Dd, w_h_a, Dd, Hh, 1024, wh, Bb * Tt);
    // Node 2: s0 partials = h[:,0,:] @ w_init_s^T (4 k-splits)
    gemm_part<<<dim3(16, 1, 4), 256>>>(h, Tt * Dd, w_init_s, Dd, Hh, 256, pproj, Bb);
    // Node 3: s0 = tanh(partials + bias); y0 = 0
    init_state_kernel<<<512, 256>>>(b_init_s);
    // Node 4: the whole recurrence
    persist_kernel<<<NBLK, 256>>>(h, w_s_a, b_s_a, w_a,
                                  gru_w_ih, gru_w_hh, gru_b_ih, gru_b_hh,
                                  rnn_w_ih, rnn_w_hh, rnn_b_ih, rnn_b_hh, out);
    (void)in_sizes; (void)n_in; (void)out_size;
}

// round 3
// speedup vs baseline: 1.0179x; 1.0179x over previous
#include <cuda_runtime.h>
#include <cuda_bf16.h>

#define Bb 128
#define Tt 256
#define Dd 1024
#define Hh 1024
#define Vv 1024
#define Ss 128
#define H3 3072
#define NBLK 296

// ---------------- scratch (device globals; no cudaMalloc allowed) -----------
__device__ __align__(16) float g_wh[(long)Bb * Tt * Hh];     // 134 MB
__device__ __align__(16) float g_part_proj[4 * Bb * Hh];
__device__ __align__(16) float g_part_gi[6 * Bb * H3];
__device__ __align__(16) float g_part_gh[2 * Bb * H3];
__device__ __align__(16) float g_part_pre[14 * Bb * Vv];
__device__ __align__(16) float g_xcat[Bb * 2048];            // [c | y]
__device__ __align__(16) float g_xr[Bb * 2048];              // [c | s_new]
__device__ __align__(16) float g_s[Bb * Hh];

// barrier state
__device__ unsigned g_bar_count = 0;
__device__ unsigned g_bar_gen = 0;

// ---------------- MUFU-based math -------------------------------------------
__device__ __forceinline__ float ex2_approx(float x) {
    float r; asm("ex2.approx.ftz.f32 %0, %1;" : "=f"(r) : "f"(x)); return r;
}
__device__ __forceinline__ float rcp_approx(float x) {
    float r; asm("rcp.approx.ftz.f32 %0, %1;" : "=f"(r) : "f"(x)); return r;
}
__device__ __forceinline__ float exp_mufu(float x) {
    return ex2_approx(x * 1.4426950408889634f);
}
__device__ __forceinline__ float tanh_mufu(float x) {
    float ax = fabsf(x);
    float e  = ex2_approx(ax * -2.885390081777927f);   // e^{-2|x|}
    float r  = rcp_approx(1.0f + e);
    float th = fmaf(-2.0f * e, r, 1.0f);
    return copysignf(th, x);
}
__device__ __forceinline__ float sigmoid_mufu(float x) {
    float e = ex2_approx(x * -1.4426950408889634f);
    return rcp_approx(1.0f + e);
}

__device__ __forceinline__ float warp_sum(float v) {
#pragma unroll
    for (int o = 16; o > 0; o >>= 1) v += __shfl_xor_sync(0xffffffffu, v, o);
    return v;
}
__device__ __forceinline__ float warp_max(float v) {
#pragma unroll
    for (int o = 16; o > 0; o >>= 1) v = fmaxf(v, __shfl_xor_sync(0xffffffffu, v, o));
    return v;
}

// ---------------- grid barrier ----------------------------------------------
__device__ __forceinline__ void grid_barrier(unsigned nblk) {
    __syncthreads();
    if (threadIdx.x == 0) {
        volatile unsigned* genp = &g_bar_gen;
        unsigned gen = *genp;
        __threadfence();
        unsigned arrived = atomicAdd(&g_bar_count, 1u);
        if (arrived == nblk - 1u) {
            *(volatile unsigned*)&g_bar_count = 0u;
            __threadfence();
            atomicExch(&g_bar_gen, gen + 1u);
        } else {
            while (*genp == gen) { }
        }
        __threadfence();
    }
    __syncthreads();
}

// ---------------- double-buffered 128x64 GEMM tile ---------------------------
// C[m,n] = sum_k A[m,k]*Bw[n,k]; m in [0,128); n tile of 64; kcount % 16 == 0.
__device__ __forceinline__ void gemm_tile(
    const float* __restrict__ A, int lda,
    const float* __restrict__ Bw, int ldb,
    int kcount,
    float* __restrict__ C, int ldc,
    float (*As)[16][132], float (*Bs)[16][68])
{
    const int tid = threadIdx.x;
    const int tx = tid & 15, ty = tid >> 4;
    const int am = tid >> 1, ak = (tid & 1) * 8;
    const int bn = tid >> 2, bk = (tid & 3) * 4;
    const float* Ap = A + (long)am * lda + ak;
    const float* Bp = Bw + (long)bn * ldb + bk;

    float acc[8][4];
#pragma unroll
    for (int i = 0; i < 8; i++)
#pragma unroll
        for (int j = 0; j < 4; j++) acc[i][j] = 0.0f;

    float4 a0 = *(const float4*)(Ap);
    float4 a1 = *(const float4*)(Ap + 4);
    float4 b0 = *(const float4*)(Bp);
    As[0][ak + 0][am] = a0.x; As[0][ak + 1][am] = a0.y;
    As[0][ak + 2][am] = a0.z; As[0][ak + 3][am] = a0.w;
    As[0][ak + 4][am] = a1.x; As[0][ak + 5][am] = a1.y;
    As[0][ak + 6][am] = a1.z; As[0][ak + 7][am] = a1.w;
    Bs[0][bk + 0][bn] = b0.x; Bs[0][bk + 1][bn] = b0.y;
    Bs[0][bk + 2][bn] = b0.z; Bs[0][bk + 3][bn] = b0.w;
    __syncthreads();

    int buf = 0;
    for (int kt = 0; kt < kcount; kt += 16) {
        bool more = (kt + 16) < kcount;
        if (more) {
            a0 = *(const float4*)(Ap + kt + 16);
            a1 = *(const float4*)(Ap + kt + 20);
            b0 = *(const float4*)(Bp + kt + 16);
        }
#pragma unroll
        for (int k = 0; k < 16; k++) {
            float a[8], b[4];
            *(float4*)&a[0] = *(const float4*)&As[buf][k][ty * 8];
            *(float4*)&a[4] = *(const float4*)&As[buf][k][ty * 8 + 4];
            *(float4*)&b[0] = *(const float4*)&Bs[buf][k][tx * 4];
#pragma unroll
            for (int i = 0; i < 8; i++)
#pragma unroll
                for (int j = 0; j < 4; j++)
                    acc[i][j] = fmaf(a[i], b[j], acc[i][j]);
        }
        if (more) {
            int nb = buf ^ 1;
            As[nb][ak + 0][am] = a0.x; As[nb][ak + 1][am] = a0.y;
            As[nb][ak + 2][am] = a0.z; As[nb][ak + 3][am] = a0.w;
            As[nb][ak + 4][am] = a1.x; As[nb][ak + 5][am] = a1.y;
            As[nb][ak + 6][am] = a1.z; As[nb][ak + 7][am] = a1.w;
            Bs[nb][bk + 0][bn] = b0.x; Bs[nb][bk + 1][bn] = b0.y;
            Bs[nb][bk + 2][bn] = b0.z; Bs[nb][bk + 3][bn] = b0.w;
        }
        __syncthreads();
        buf ^= 1;
    }
#pragma unroll
    for (int i = 0; i < 8; i++) {
        float4 o = make_float4(acc[i][0], acc[i][1], acc[i][2], acc[i][3]);
        *(float4*)(C + (long)(ty * 8 + i) * ldc + tx * 4) = o;
    }
}

// ---------------- standalone GEMM kernel (wh precompute / s0) ----------------
__global__ void __launch_bounds__(256, 2)
gemm_part(const float* __restrict__ A, int lda,
          const float* __restrict__ Bw, int ldb,
          int N, int ksplit,
          float* __restrict__ Cp, int mtot)
{
    __shared__ __align__(16) float As[2][16][132];
    __shared__ __align__(16) float Bs[2][16][68];
    const int nb = blockIdx.x, mb = blockIdx.y, z = blockIdx.z;
    const int k0 = z * ksplit;
    gemm_tile(A + (long)(mb * 128) * lda + k0, lda,
              Bw + (long)(nb * 64) * ldb + k0, ldb,
              ksplit,
              Cp + ((long)z * mtot + mb * 128) * N + nb * 64, N,
              As, Bs);
}

// s0 = tanh(sum of 4 partial slots + bias); y0 = 0
__global__ void init_state_kernel(const float* __restrict__ bias)
{
    int idx = blockIdx.x * 256 + threadIdx.x;   // < 128*1024
    int b = idx >> 10, hh = idx & 1023;
    float v = bias[hh];
#pragma unroll
    for (int q = 0; q < 4; q++) v += g_part_proj[q * (Bb * Hh) + idx];
    g_s[idx] = tanh_mufu(v);
    g_xcat[b * 2048 + 1024 + hh] = 0.0f;        // y = 0
}

// ---------------- the persistent kernel --------------------------------------
__global__ void __launch_bounds__(256, 2)
persist_kernel(const float* __restrict__ h,
               const float* __restrict__ w_s_a, const float* __restrict__ b_s_a,
               const float* __restrict__ w_a,
               const float* __restrict__ gru_w_ih, const float* __restrict__ gru_w_hh,
               const float* __restrict__ gru_b_ih, const float* __restrict__ gru_b_hh,
               const float* __restrict__ rnn_w_ih, const float* __restrict__ rnn_w_hh,
               const float* __restrict__ rnn_b_ih, const float* __restrict__ rnn_b_hh,
               float* __restrict__ out)
{
    __shared__ __align__(16) float As[2][16][132];
    __shared__ __align__(16) float Bs[2][16][68];
    __shared__ float s_bc;

    const int blk = blockIdx.x;
    const int tid = threadIdx.x;
    const int w = tid >> 5, l = tid & 31;

    float* p_sh = &As[0][0][0];       // 1024 floats
    float* w_sh = p_sh + 1024;        // 1024 floats (As = 4224 floats)
    float* sc   = &Bs[0][0][0];       // 256 floats
    float* red  = sc + 256;           // 8 floats

    for (int step = 0; step < Ss; step++) {
        // ==== Phase ALPHA: proj + gh + gi_y + pre_hh (all ready post prev step)
        if (blk < 64) {                 // proj = s @ w_s_a^T : 16nt x 4z, K=256
            int nt = blk & 15, z = blk >> 4;
            gemm_tile(g_s + z * 256, Hh,
                      w_s_a + (long)(nt * 64) * Hh + z * 256, Hh, 256,
                      g_part_proj + z * (Bb * Hh) + nt * 64, Hh, As, Bs);
        } else if (blk < 160) {         // gh = s @ gru_w_hh^T : 48nt x 2z, K=512
            int i = blk - 64, nt = i >> 1, z = i & 1;
            gemm_tile(g_s + z * 512, Hh,
                      gru_w_hh + (long)(nt * 64) * Hh + z * 512, Hh, 512,
                      g_part_gh + (long)z * (Bb * H3) + nt * 64, H3, As, Bs);
        } else if (blk < 256) {         // gi_y = y @ Wih[:,1024:]^T : 48nt x 2z
            int i = blk - 160, nt = i >> 1, z = i & 1;
            gemm_tile(g_xcat + 1024 + z * 512, 2048,
                      gru_w_ih + (long)(nt * 64) * 2048 + 1024 + z * 512, 2048, 512,
                      g_part_gi + (long)z * (Bb * H3) + nt * 64, H3, As, Bs);
        } else if (blk < 288) {         // pre_hh = y @ rnn_w_hh^T : 16nt x 2z
            int i = blk - 256, nt = i & 15, z = i >> 4;
            gemm_tile(g_xcat + 1024 + z * 512, 2048,
                      rnn_w_hh + (long)(nt * 64) * Hh + z * 512, Hh, 512,
                      g_part_pre + (long)(12 + z) * (Bb * Vv) + nt * 64, Vv, As, Bs);
        }
        grid_barrier(NBLK);

        // ==== Phase BETA: attention (reduce proj, scores, softmax, ctx)
        if (blk < 128) {
            int b = blk;
            {
                float4 acc = ((const float4*)b_s_a)[tid];
#pragma unroll
                for (int z = 0; z < 4; z++) {
                    float4 v = ((const float4*)(g_part_proj + z * (Bb * Hh) + b * Hh))[tid];
                    acc.x += v.x; acc.y += v.y; acc.z += v.z; acc.w += v.w;
                }
                ((float4*)p_sh)[tid] = acc;
                ((float4*)w_sh)[tid] = ((const float4*)w_a)[tid];
            }
            __syncthreads();
            const float4* whb = (const float4*)(g_wh + (long)b * Tt * Hh);
            for (int tt = 0; tt < 32; tt++) {
                int t = w * 32 + tt;
                const float4* whp = whb + (long)t * 256;
                float acc = 0.0f;
#pragma unroll
                for (int jj = 0; jj < 8; jj++) {
                    int fi = jj * 32 + l;
                    float4 v  = whp[fi];
                    float4 p  = ((const float4*)p_sh)[fi];
                    float4 wa = ((const float4*)w_sh)[fi];
                    acc = fmaf(tanh_mufu(v.x + p.x), wa.x, acc);
                    acc = fmaf(tanh_mufu(v.y + p.y), wa.y, acc);
                    acc = fmaf(tanh_mufu(v.z + p.z), wa.z, acc);
                    acc = fmaf(tanh_mufu(v.w + p.w), wa.w, acc);
                }
                acc = warp_sum(acc);
                if (l == 0) sc[t] = acc;
            }
            __syncthreads();
            {   // softmax over sc[256]
                float v = sc[tid];
                float m = warp_max(v);
                if (l == 0) red[w] = m;
                __syncthreads();
                if (tid == 0) {
                    float mm = red[0];
#pragma unroll
                    for (int i = 1; i < 8; i++) mm = fmaxf(mm, red[i]);
                    s_bc = mm;
                }
                __syncthreads();
                float e = exp_mufu(v - s_bc);
                float s = warp_sum(e);
                if (l == 0) red[w] = s;
                __syncthreads();
                if (tid == 0) {
                    float ss = 0.0f;
#pragma unroll
                    for (int i = 0; i < 8; i++) ss += red[i];
                    s_bc = rcp_approx(ss);
                }
                __syncthreads();
                sc[tid] = e * s_bc;
            }
            __syncthreads();
            {   // ctx
                const float4* hp = (const float4*)(h + (long)b * Tt * Dd);
                float4 c = make_float4(0.f, 0.f, 0.f, 0.f);
#pragma unroll 4
                for (int t = 0; t < Tt; t++) {
                    float a = sc[t];
                    float4 v = hp[(long)t * 256 + tid];
                    c.x = fmaf(a, v.x, c.x); c.y = fmaf(a, v.y, c.y);
                    c.z = fmaf(a, v.z, c.z); c.w = fmaf(a, v.w, c.w);
                }
                ((float4*)(g_xcat + b * 2048))[tid] = c;
                ((float4*)(g_xr   + b * 2048))[tid] = c;
            }
        }
        grid_barrier(NBLK);

        // ==== Phase GAMMA: gi_c + pre_ih_c (need c from beta)
        if (blk < 192) {                // gi_c = c @ Wih[:, :1024]^T : 48nt x 4z
            int nt = blk >> 2, z = blk & 3;
            gemm_tile(g_xcat + z * 256, 2048,
                      gru_w_ih + (long)(nt * 64) * 2048 + z * 256, 2048, 256,
                      g_part_gi + (long)(2 + z) * (Bb * H3) + nt * 64, H3, As, Bs);
        } else if (blk < 256) {         // pre_ih_c = c @ rnn_w_ih[:, :1024]^T
            int i = blk - 192, nt = i >> 2, z = i & 3;
            gemm_tile(g_xr + z * 256, 2048,
                      rnn_w_ih + (long)(nt * 64) * 2048 + z * 256, 2048, 256,
                      g_part_pre + (long)z * (Bb * Vv) + nt * 64, Vv, As, Bs);
        }
        grid_barrier(NBLK);

        // ==== Phase DELTA: GRU elementwise
        for (int idx = blk * 256 + tid; idx < Bb * Hh; idx += NBLK * 256) {
            int b = idx >> 10, hh = idx & 1023;
            float gir = gru_b_ih[hh], giz = gru_b_ih[1024 + hh], gin = gru_b_ih[2048 + hh];
#pragma unroll
            for (int q = 0; q < 6; q++) {
                const float* p = g_part_gi + (long)(q * Bb + b) * H3 + hh;
                gir += p[0]; giz += p[1024]; gin += p[2048];
            }
            float ghr = gru_b_hh[hh], ghz = gru_b_hh[1024 + hh], ghn = gru_b_hh[2048 + hh];
#pragma unroll
            for (int q = 0; q < 2; q++) {
                const float* p = g_part_gh + (long)(q * Bb + b) * H3 + hh;
                ghr += p[0]; ghz += p[1024]; ghn += p[2048];
            }
            float r = sigmoid_mufu(gir + ghr);
            float z = sigmoid_mufu(giz + ghz);
            float n = tanh_mufu(fmaf(r, ghn, gin));
            float sv = g_s[idx];
            float sn = fmaf(z, sv - n, n);
            g_s[idx] = sn;
            g_xr[b * 2048 + 1024 + hh] = sn;
        }
        grid_barrier(NBLK);

        // ==== Phase EPSILON: pre_ih_s = s_new @ rnn_w_ih[:,1024:]^T : 16nt x 8z
        if (blk < 128) {
            int nt = blk >> 3, z = blk & 7;
            gemm_tile(g_xr + 1024 + z * 128, 2048,
                      rnn_w_ih + (long)(nt * 64) * 2048 + 1024 + z * 128, 2048, 128,
                      g_part_pre + (long)(4 + z) * (Bb * Vv) + nt * 64, Vv, As, Bs);
        }
        grid_barrier(NBLK);

        // ==== Phase ZETA: out = softmax(tanh(pre)); store y + output
        if (blk < 128) {
            int b = blk;
            float4 acc = ((const float4*)rnn_b_ih)[tid];
            float4 b2  = ((const float4*)rnn_b_hh)[tid];
            acc.x += b2.x; acc.y += b2.y; acc.z += b2.z; acc.w += b2.w;
#pragma unroll
            for (int q = 0; q < 14; q++) {
                float4 p = ((const float4*)(g_part_pre + (long)q * (Bb * Vv) + b * Vv))[tid];
                acc.x += p.x; acc.y += p.y; acc.z += p.z; acc.w += p.w;
            }
            float t0 = tanh_mufu(acc.x), t1 = tanh_mufu(acc.y);
            float t2 = tanh_mufu(acc.z), t3 = tanh_mufu(acc.w);
            float m = fmaxf(fmaxf(t0, t1), fmaxf(t2, t3));
            m = warp_max(m);
            if (l == 0) red[w] = m;
            __syncthreads();
            if (tid == 0) {
                float mm = red[0];
#pragma unroll
                for (int i = 1; i < 8; i++) mm = fmaxf(mm, red[i]);
                s_bc = mm;
            }
            __syncthreads();
            float mx = s_bc;
            float e0 = exp_mufu(t0 - mx), e1 = exp_mufu(t1 - mx);
            float e2 = exp_mufu(t2 - mx), e3 = exp_mufu(t3 - mx);
            float s = warp_sum(e0 + e1 + e2 + e3);
            if (l == 0) red[w] = s;
            __syncthreads();
            if (tid == 0) {
                float ss = 0.0f;
#pragma unroll
                for (int i = 0; i < 8; i++) ss += red[i];
                s_bc = rcp_approx(ss);
            }
            __syncthreads();
            float inv = s_bc;
            float4 y = make_float4(e0 * inv, e1 * inv, e2 * inv, e3 * inv);
            ((float4*)(g_xcat + b * 2048 + 1024))[tid] = y;
            ((float4*)(out + ((long)b * Ss + step) * Vv))[tid] = y;
        }
        grid_barrier(NBLK);   // zeta -> next alpha (alpha reads y, s)
    }
}

// ---------------- launcher ----------------------------------------------------
extern "C" void kernel_launch(void* const* d_in, const int* in_sizes, int n_in,
                              void* d_out, int out_size)
{
    const float* h        = (const float*)d_in[0];
    const float* w_h_a    = (const float*)d_in[1];
    const float* w_s_a    = (const float*)d_in[2];
    const float* b_s_a    = (const float*)d_in[3];
    const float* w_a      = (const float*)d_in[4];
    const float* w_init_s = (const float*)d_in[5];
    const float* b_init_s = (const float*)d_in[6];
    const float* gru_w_ih = (const float*)d_in[7];
    const float* gru_w_hh = (const float*)d_in[8];
    const float* gru_b_ih = (const float*)d_in[9];
    const float* gru_b_hh = (const float*)d_in[10];
    const float* rnn_w_ih = (const float*)d_in[11];
    const float* rnn_w_hh = (const float*)d_in[12];
    const float* rnn_b_ih = (const float*)d_in[13];
    const float* rnn_b_hh = (const float*)d_in[14];
    float* out = (float*)d_out;

    float *wh, *pproj;
    cudaGetSymbolAddress((void**)&wh,    g_wh);
    cudaGetSymbolAddress((void**)&pproj, g_part_proj);

    // Node 1: wh = h @ w_h_a^T (M = 32768, full K)
    gemm_part<<<dim3(16, 256, 1), 256>>>(h, Dd, w_h_a, Dd, Hh, 1024, wh, Bb * Tt);
    // Node 2: s0 partials = h[:,0,:] @ w_init_s^T (4 k-splits of 256)
    gemm_part<<<dim3(16, 1, 4), 256>>>(h, Tt * Dd, w_init_s, Dd, Hh, 256, pproj, Bb);
    // Node 3: s0 = tanh(partials + bias); y0 = 0
    init_state_kernel<<<512, 256>>>(b_init_s);
    // Node 4: the recurrence (296 co-resident blocks; 2 CTAs/SM guaranteed by
    //         __launch_bounds__(256, 2))
    persist_kernel<<<NBLK, 256>>>(h, w_s_a, b_s_a, w_a,
                                  gru_w_ih, gru_w_hh, gru_b_ih, gru_b_hh,
                                  rnn_w_ih, rnn_w_hh, rnn_b_ih, rnn_b_hh, out);
    (void)in_sizes; (void)n_in; (void)out_size;
}

// round 4
// speedup vs baseline: 1.3393x; 1.3158x over previous
#include <cuda_runtime.h>
#include <cuda_bf16.h>

#define Bb 128
#define Tt 256
#define Dd 1024
#define Hh 1024
#define Vv 1024
#define Ss 128
#define H3 3072
#define NBLK 296
#define PITCH 24   // bf16 elems per smem row: 48B, 16B-aligned, conflict-free LDSM

// ---------------- scratch (device globals; no cudaMalloc allowed) -----------
__device__ __align__(16) float g_wh[(long)Bb * Tt * Hh];     // 134 MB fp32
__device__ __align__(16) float g_part_proj[4 * Bb * Hh];
__device__ __align__(16) float g_part_gi[6 * Bb * H3];
__device__ __align__(16) float g_part_gh[2 * Bb * H3];
__device__ __align__(16) float g_part_pre[14 * Bb * Vv];
__device__ __align__(16) float g_s[Bb * Hh];                 // fp32 state

// split-bf16 mirrors: value = hi + lo
__device__ __align__(16) __nv_bfloat16 g_s_h[Bb * Hh], g_s_l[Bb * Hh];
__device__ __align__(16) __nv_bfloat16 g_c_h[Bb * Hh], g_c_l[Bb * Hh];
__device__ __align__(16) __nv_bfloat16 g_y_h[Bb * Hh], g_y_l[Bb * Hh];
// weights
__device__ __align__(16) __nv_bfloat16 g_wsa_h[1024 * 1024], g_wsa_l[1024 * 1024];
__device__ __align__(16) __nv_bfloat16 g_gwh_h[3072 * 1024], g_gwh_l[3072 * 1024];
__device__ __align__(16) __nv_bfloat16 g_gwi_h[(long)3072 * 2048], g_gwi_l[(long)3072 * 2048];
__device__ __align__(16) __nv_bfloat16 g_rwi_h[(long)1024 * 2048], g_rwi_l[(long)1024 * 2048];
__device__ __align__(16) __nv_bfloat16 g_rwh_h[1024 * 1024], g_rwh_l[1024 * 1024];
__device__ __align__(16) __nv_bfloat16 g_wha_h[1024 * 1024], g_wha_l[1024 * 1024];
__device__ __align__(16) __nv_bfloat16 g_wis_h[1024 * 1024], g_wis_l[1024 * 1024];
__device__ __align__(16) __nv_bfloat16 g_h_h[(long)Bb * Tt * Dd], g_h_l[(long)Bb * Tt * Dd];

// barrier state
__device__ unsigned g_bar_count = 0;
__device__ unsigned g_bar_gen = 0;

// ---------------- math helpers -----------------------------------------------
__device__ __forceinline__ float ex2_approx(float x) {
    float r; asm("ex2.approx.ftz.f32 %0, %1;" : "=f"(r) : "f"(x)); return r;
}
__device__ __forceinline__ float rcp_approx(float x) {
    float r; asm("rcp.approx.ftz.f32 %0, %1;" : "=f"(r) : "f"(x)); return r;
}
__device__ __forceinline__ float exp_mufu(float x) {
    return ex2_approx(x * 1.4426950408889634f);
}
__device__ __forceinline__ float tanh_mufu(float x) {
    float ax = fabsf(x);
    float e  = ex2_approx(ax * -2.885390081777927f);
    float r  = rcp_approx(1.0f + e);
    float th = fmaf(-2.0f * e, r, 1.0f);
    return copysignf(th, x);
}
__device__ __forceinline__ float sigmoid_mufu(float x) {
    float e = ex2_approx(x * -1.4426950408889634f);
    return rcp_approx(1.0f + e);
}
__device__ __forceinline__ float warp_sum(float v) {
#pragma unroll
    for (int o = 16; o > 0; o >>= 1) v += __shfl_xor_sync(0xffffffffu, v, o);
    return v;
}
__device__ __forceinline__ float warp_max(float v) {
#pragma unroll
    for (int o = 16; o > 0; o >>= 1) v = fmaxf(v, __shfl_xor_sync(0xffffffffu, v, o));
    return v;
}
__device__ __forceinline__ void split_w(float v, __nv_bfloat16* hi, __nv_bfloat16* lo, long i) {
    __nv_bfloat16 hb = __float2bfloat16(v);
    hi[i] = hb;
    lo[i] = __float2bfloat16(v - __bfloat162float(hb));
}

// ---------------- grid barrier ------------------------------------------------
__device__ __forceinline__ void grid_barrier(unsigned nblk) {
    __syncthreads();
    if (threadIdx.x == 0) {
        volatile unsigned* genp = &g_bar_gen;
        unsigned gen = *genp;
        __threadfence();
        unsigned arrived = atomicAdd(&g_bar_count, 1u);
        if (arrived == nblk - 1u) {
            *(volatile unsigned*)&g_bar_count = 0u;
            __threadfence();
            atomicExch(&g_bar_gen, gen + 1u);
        } else {
            while (*genp == gen) { }
        }
        __threadfence();
    }
    __syncthreads();
}

// ---------------- tensor-core primitives ---------------------------------------
__device__ __forceinline__ void mma16816(float* d, const unsigned* a, const unsigned* b) {
    asm volatile(
        "mma.sync.aligned.m16n8k16.row.col.f32.bf16.bf16.f32 "
        "{%0,%1,%2,%3}, {%4,%5,%6,%7}, {%8,%9}, {%0,%1,%2,%3};\n"
        : "+f"(d[0]), "+f"(d[1]), "+f"(d[2]), "+f"(d[3])
        : "r"(a[0]), "r"(a[1]), "r"(a[2]), "r"(a[3]), "r"(b[0]), "r"(b[1]));
}
__device__ __forceinline__ void ldsm4(unsigned* r, const void* p) {
    unsigned addr = (unsigned)__cvta_generic_to_shared(p);
    asm volatile("ldmatrix.sync.aligned.m8n8.x4.shared.b16 {%0,%1,%2,%3}, [%4];\n"
                 : "=r"(r[0]), "=r"(r[1]), "=r"(r[2]), "=r"(r[3]) : "r"(addr));
}

struct SmemTC {
    __nv_bfloat16 Ah[2][128][PITCH];
    __nv_bfloat16 Al[2][128][PITCH];
    __nv_bfloat16 Bh[2][64][PITCH];
    __nv_bfloat16 Bl[2][64][PITCH];
};   // 36864 B

// C[128 m][64 n] = sum_k A[m,k]*B[n,k] in split-bf16 (3 MMAs), fp32 accumulate.
// kcount % 16 == 0. 256 threads, 8 warps: warp = (m half 32) x (n half 32).
__device__ void gemm_tc(const __nv_bfloat16* __restrict__ Ah,
                        const __nv_bfloat16* __restrict__ Al, long lda,
                        const __nv_bfloat16* __restrict__ Bh,
                        const __nv_bfloat16* __restrict__ Bl, long ldb,
                        int kcount, float* __restrict__ C, int ldc, SmemTC* sm)
{
    const int tid = threadIdx.x;
    const int lane = tid & 31, wp = tid >> 5;
    const int m0 = (wp & 3) * 32, n0 = (wp >> 2) * 32;

    const int ar = tid >> 1, ac = (tid & 1) * 8;          // A: 2 thr/row
    const int br = (tid & 127) >> 1, bc2 = (tid & 1) * 8; // B: 2 thr/row per half
    const bool blo = tid >= 128;
    const __nv_bfloat16* Bsrc = blo ? Bl : Bh;

    uint4 pah = *(const uint4*)(Ah + (long)ar * lda + ac);
    uint4 pal = *(const uint4*)(Al + (long)ar * lda + ac);
    uint4 pb  = *(const uint4*)(Bsrc + (long)br * ldb + bc2);

    float acc[2][4][4];
#pragma unroll
    for (int i = 0; i < 2; i++)
#pragma unroll
        for (int j = 0; j < 4; j++)
#pragma unroll
            for (int k = 0; k < 4; k++) acc[i][j][k] = 0.0f;

    const int arow = lane & 15;
    const int acol = (lane & 16) ? 8 : 0;
    const int brow = (lane & 7) + ((lane & 16) ? 8 : 0);
    const int bcol = (lane & 8) ? 8 : 0;

    int buf = 0;
    for (int kt = 0; kt < kcount; kt += 16) {
        *(uint4*)&sm->Ah[buf][ar][ac] = pah;
        *(uint4*)&sm->Al[buf][ar][ac] = pal;
        if (!blo) *(uint4*)&sm->Bh[buf][br][bc2] = pb;
        else      *(uint4*)&sm->Bl[buf][br][bc2] = pb;
        __syncthreads();
        if (kt + 16 < kcount) {
            pah = *(const uint4*)(Ah + (long)ar * lda + kt + 16 + ac);
            pal = *(const uint4*)(Al + (long)ar * lda + kt + 16 + ac);
            pb  = *(const uint4*)(Bsrc + (long)br * ldb + kt + 16 + bc2);
        }
        unsigned afh[2][4], afl[2][4];
#pragma unroll
        for (int mt = 0; mt < 2; mt++) {
            ldsm4(afh[mt], &sm->Ah[buf][m0 + mt * 16 + arow][acol]);
            ldsm4(afl[mt], &sm->Al[buf][m0 + mt * 16 + arow][acol]);
        }
        unsigned bfh[4][2], bfl[4][2];
#pragma unroll
        for (int hf = 0; hf < 2; hf++) {
            unsigned r[4];
            ldsm4(r, &sm->Bh[buf][n0 + hf * 16 + brow][bcol]);
            bfh[2*hf][0] = r[0]; bfh[2*hf][1] = r[1];
            bfh[2*hf+1][0] = r[2]; bfh[2*hf+1][1] = r[3];
            ldsm4(r, &sm->Bl[buf][n0 + hf * 16 + brow][bcol]);
            bfl[2*hf][0] = r[0]; bfl[2*hf][1] = r[1];
            bfl[2*hf+1][0] = r[2]; bfl[2*hf+1][1] = r[3];
        }
#pragma unroll
        for (int mt = 0; mt < 2; mt++)
#pragma unroll
            for (int nt = 0; nt < 4; nt++) {
                mma16816(acc[mt][nt], afh[mt], bfh[nt]);
                mma16816(acc[mt][nt], afh[mt], bfl[nt]);
                mma16816(acc[mt][nt], afl[mt], bfh[nt]);
            }
        buf ^= 1;
    }
    const int gr = lane >> 2, gc = (lane & 3) * 2;
#pragma unroll
    for (int mt = 0; mt < 2; mt++)
#pragma unroll
        for (int nt = 0; nt < 4; nt++) {
            long base = (long)(m0 + mt * 16 + gr) * ldc + n0 + nt * 8 + gc;
            *(float2*)&C[base]           = make_float2(acc[mt][nt][0], acc[mt][nt][1]);
            *(float2*)&C[base + 8 * ldc] = make_float2(acc[mt][nt][2], acc[mt][nt][3]);
        }
}

// ---------------- prep kernels --------------------------------------------------
__global__ void conv_split(const float* __restrict__ x, __nv_bfloat16* __restrict__ hi,
                           __nv_bfloat16* __restrict__ lo, long n)
{
    long i = (long)blockIdx.x * blockDim.x + threadIdx.x;
    long stride = (long)gridDim.x * blockDim.x;
    for (; i < n; i += stride) {
        float v = x[i];
        __nv_bfloat16 hb = __float2bfloat16(v);
        hi[i] = hb;
        lo[i] = __float2bfloat16(v - __bfloat162float(hb));
    }
}

__global__ void __launch_bounds__(256, 2) wh_gemm_kernel()
{
    __shared__ __align__(16) SmemTC sm;
    int nt = blockIdx.x, mb = blockIdx.y;
    gemm_tc(g_h_h + (long)mb * 128 * 1024, g_h_l + (long)mb * 128 * 1024, 1024,
            g_wha_h + (long)nt * 64 * 1024, g_wha_l + (long)nt * 64 * 1024, 1024,
            1024, g_wh + (long)mb * 128 * 1024 + nt * 64, 1024, &sm);
}

__global__ void __launch_bounds__(256, 2) s0_gemm_kernel()
{
    __shared__ __align__(16) SmemTC sm;
    int nt = blockIdx.x, z = blockIdx.y;   // 4 k-splits of 256; A rows stride T*D
    gemm_tc(g_h_h + z * 256, g_h_l + z * 256, (long)Tt * Dd,
            g_wis_h + (long)nt * 64 * 1024 + z * 256,
            g_wis_l + (long)nt * 64 * 1024 + z * 256, 1024,
            256, g_part_proj + z * (Bb * Hh) + nt * 64, 1024, &sm);
}

__global__ void init_state_kernel(const float* __restrict__ bias)
{
    int idx = blockIdx.x * 256 + threadIdx.x;   // < 128*1024
    int hh = idx & 1023;
    float v = bias[hh];
#pragma unroll
    for (int q = 0; q < 4; q++) v += g_part_proj[q * (Bb * Hh) + idx];
    float s = tanh_mufu(v);
    g_s[idx] = s;
    split_w(s, g_s_h, g_s_l, idx);
    g_y_h[idx] = __float2bfloat16(0.0f);
    g_y_l[idx] = __float2bfloat16(0.0f);
}

// ---------------- the persistent kernel -----------------------------------------
__global__ void __launch_bounds__(256, 2)
persist_kernel(const float* __restrict__ h,
               const float* __restrict__ b_s_a, const float* __restrict__ w_a,
               const float* __restrict__ gru_b_ih, const float* __restrict__ gru_b_hh,
               const float* __restrict__ rnn_b_ih, const float* __restrict__ rnn_b_hh,
               float* __restrict__ out)
{
    __shared__ __align__(16) unsigned char sraw[sizeof(SmemTC)];
    __shared__ float s_bc;
    SmemTC* sm = (SmemTC*)sraw;
    float* p_sh = (float*)sraw;        // 1024 floats (attention phase only)
    float* w_sh = p_sh + 1024;         // 1024
    float* sc   = w_sh + 1024;         // 256
    float* red  = sc + 256;            // 8      total 9216B < 36864B

    const int blk = blockIdx.x;
    const int tid = threadIdx.x;
    const int w = tid >> 5, l = tid & 31;

    for (int step = 0; step < Ss; step++) {
        // ==== ALPHA: proj + gh + gi_y + pre_hh
        if (blk < 64) {                 // proj = s @ w_s_a^T : 16nt x 4z, K=256
            int nt = blk & 15, z = blk >> 4;
            gemm_tc(g_s_h + z * 256, g_s_l + z * 256, 1024,
                    g_wsa_h + (long)nt * 64 * 1024 + z * 256,
                    g_wsa_l + (long)nt * 64 * 1024 + z * 256, 1024,
                    256, g_part_proj + z * (Bb * Hh) + nt * 64, Hh, sm);
        } else if (blk < 160) {         // gh = s @ gru_w_hh^T : 48nt x 2z, K=512
            int i = blk - 64, nt = i >> 1, z = i & 1;
            gemm_tc(g_s_h + z * 512, g_s_l + z * 512, 1024,
                    g_gwh_h + (long)nt * 64 * 1024 + z * 512,
                    g_gwh_l + (long)nt * 64 * 1024 + z * 512, 1024,
                    512, g_part_gh + (long)z * (Bb * H3) + nt * 64, H3, sm);
        } else if (blk < 256) {         // gi_y = y @ Wih[:,1024:]^T : 48nt x 2z
            int i = blk - 160, nt = i >> 1, z = i & 1;
            gemm_tc(g_y_h + z * 512, g_y_l + z * 512, 1024,
                    g_gwi_h + (long)nt * 64 * 2048 + 1024 + z * 512,
                    g_gwi_l + (long)nt * 64 * 2048 + 1024 + z * 512, 2048,
                    512, g_part_gi + (long)z * (Bb * H3) + nt * 64, H3, sm);
        } else if (blk < 288) {         // pre_hh = y @ rnn_w_hh^T : 16nt x 2z
            int i = blk - 256, nt = i & 15, z = i >> 4;
            gemm_tc(g_y_h + z * 512, g_y_l + z * 512, 1024,
                    g_rwh_h + (long)nt * 64 * 1024 + z * 512,
                    g_rwh_l + (long)nt * 64 * 1024 + z * 512, 1024,
                    512, g_part_pre + (long)(12 + z) * (Bb * Vv) + nt * 64, Vv, sm);
        }
        grid_barrier(NBLK);

        // ==== BETA: attention
        if (blk < 128) {
            int b = blk;
            {
                float4 acc = ((const float4*)b_s_a)[tid];
#pragma unroll
                for (int z = 0; z < 4; z++) {
                    float4 v = ((const float4*)(g_part_proj + z * (Bb * Hh) + b * Hh))[tid];
                    acc.x += v.x; acc.y += v.y; acc.z += v.z; acc.w += v.w;
                }
                ((float4*)p_sh)[tid] = acc;
                ((float4*)w_sh)[tid] = ((const float4*)w_a)[tid];
            }
            __syncthreads();
            const float4* whb = (const float4*)(g_wh + (long)b * Tt * Hh);
            for (int tt = 0; tt < 32; tt++) {
                int t = w * 32 + tt;
                const float4* whp = whb + (long)t * 256;
                float acc = 0.0f;
#pragma unroll
                for (int jj = 0; jj < 8; jj++) {
                    int fi = jj * 32 + l;
                    float4 v  = whp[fi];
                    float4 p  = ((const float4*)p_sh)[fi];
                    float4 wa = ((const float4*)w_sh)[fi];
                    acc = fmaf(tanh_mufu(v.x + p.x), wa.x, acc);
                    acc = fmaf(tanh_mufu(v.y + p.y), wa.y, acc);
                    acc = fmaf(tanh_mufu(v.z + p.z), wa.z, acc);
                    acc = fmaf(tanh_mufu(v.w + p.w), wa.w, acc);
                }
                acc = warp_sum(acc);
                if (l == 0) sc[t] = acc;
            }
            __syncthreads();
            {   // softmax over sc[256]
                float v = sc[tid];
                float m = warp_max(v);
                if (l == 0) red[w] = m;
                __syncthreads();
                if (tid == 0) {
                    float mm = red[0];
#pragma unroll
                    for (int i = 1; i < 8; i++) mm = fmaxf(mm, red[i]);
                    s_bc = mm;
                }
                __syncthreads();
                float e = exp_mufu(v - s_bc);
                float s = warp_sum(e);
                if (l == 0) red[w] = s;
                __syncthreads();
                if (tid == 0) {
                    float ss = 0.0f;
#pragma unroll
                    for (int i = 0; i < 8; i++) ss += red[i];
                    s_bc = rcp_approx(ss);
                }
                __syncthreads();
                sc[tid] = e * s_bc;
            }
            __syncthreads();
            {   // ctx: c = sum_t a[t] * h[b,t,:]; write split mirrors
                const float4* hp = (const float4*)(h + (long)b * Tt * Dd);
                float4 c = make_float4(0.f, 0.f, 0.f, 0.f);
#pragma unroll 4
                for (int t = 0; t < Tt; t++) {
                    float a = sc[t];
                    float4 v = hp[(long)t * 256 + tid];
                    c.x = fmaf(a, v.x, c.x); c.y = fmaf(a, v.y, c.y);
                    c.z = fmaf(a, v.z, c.z); c.w = fmaf(a, v.w, c.w);
                }
                long base = (long)b * 1024 + tid * 4;
                split_w(c.x, g_c_h, g_c_l, base + 0);
                split_w(c.y, g_c_h, g_c_l, base + 1);
                split_w(c.z, g_c_h, g_c_l, base + 2);
                split_w(c.w, g_c_h, g_c_l, base + 3);
            }
        }
        grid_barrier(NBLK);

        // ==== GAMMA: gi_c + pre_ih_c
        if (blk < 192) {                // gi_c : 48nt x 4z, K=256
            int nt = blk >> 2, z = blk & 3;
            gemm_tc(g_c_h + z * 256, g_c_l + z * 256, 1024,
                    g_gwi_h + (long)nt * 64 * 2048 + z * 256,
                    g_gwi_l + (long)nt * 64 * 2048 + z * 256, 2048,
                    256, g_part_gi + (long)(2 + z) * (Bb * H3) + nt * 64, H3, sm);
        } else if (blk < 256) {         // pre_ih_c : 16nt x 4z, K=256
            int i = blk - 192, nt = i >> 2, z = i & 3;
            gemm_tc(g_c_h + z * 256, g_c_l + z * 256, 1024,
                    g_rwi_h + (long)nt * 64 * 2048 + z * 256,
                    g_rwi_l + (long)nt * 64 * 2048 + z * 256, 2048,
                    256, g_part_pre + (long)z * (Bb * Vv) + nt * 64, Vv, sm);
        }
        grid_barrier(NBLK);

        // ==== DELTA: GRU elementwise
        for (int idx = blk * 256 + tid; idx < Bb * Hh; idx += NBLK * 256) {
            int b = idx >> 10, hh = idx & 1023;
            float gir = gru_b_ih[hh], giz = gru_b_ih[1024 + hh], gin = gru_b_ih[2048 + hh];
#pragma unroll
            for (int q = 0; q < 6; q++) {
                const float* p = g_part_gi + (long)(q * Bb + b) * H3 + hh;
                gir += p[0]; giz += p[1024]; gin += p[2048];
            }
            float ghr = gru_b_hh[hh], ghz = gru_b_hh[1024 + hh], ghn = gru_b_hh[2048 + hh];
#pragma unroll
            for (int q = 0; q < 2; q++) {
                const float* p = g_part_gh + (long)(q * Bb + b) * H3 + hh;
                ghr += p[0]; ghz += p[1024]; ghn += p[2048];
            }
            float r = sigmoid_mufu(gir + ghr);
            float z = sigmoid_mufu(giz + ghz);
            float n = tanh_mufu(fmaf(r, ghn, gin));
            float sv = g_s[idx];
            float sn = fmaf(z, sv - n, n);
            g_s[idx] = sn;
            split_w(sn, g_s_h, g_s_l, idx);
        }
        grid_barrier(NBLK);

        // ==== EPSILON: pre_ih_s = s_new @ rnn_w_ih[:,1024:]^T : 16nt x 8z, K=128
        if (blk < 128) {
            int nt = blk >> 3, z = blk & 7;
            gemm_tc(g_s_h + z * 128, g_s_l + z * 128, 1024,
                    g_rwi_h + (long)nt * 64 * 2048 + 1024 + z * 128,
                    g_rwi_l + (long)nt * 64 * 2048 + 1024 + z * 128, 2048,
                    128, g_part_pre + (long)(4 + z) * (Bb * Vv) + nt * 64, Vv, sm);
        }
        grid_barrier(NBLK);

        // ==== ZETA: out = softmax(tanh(pre)); store y mirrors + output
        if (blk < 128) {
            int b = blk;
            float4 acc = ((const float4*)rnn_b_ih)[tid];
            float4 b2  = ((const float4*)rnn_b_hh)[tid];
            acc.x += b2.x; acc.y += b2.y; acc.z += b2.z; acc.w += b2.w;
#pragma unroll
            for (int q = 0; q < 14; q++) {
                float4 p = ((const float4*)(g_part_pre + (long)q * (Bb * Vv) + b * Vv))[tid];
                acc.x += p.x; acc.y += p.y; acc.z += p.z; acc.w += p.w;
            }
            float t0 = tanh_mufu(acc.x), t1 = tanh_mufu(acc.y);
            float t2 = tanh_mufu(acc.z), t3 = tanh_mufu(acc.w);
            float m = fmaxf(fmaxf(t0, t1), fmaxf(t2, t3));
            m = warp_max(m);
            if (l == 0) red[w] = m;
            __syncthreads();
            if (tid == 0) {
                float mm = red[0];
#pragma unroll
                for (int i = 1; i < 8; i++) mm = fmaxf(mm, red[i]);
                s_bc = mm;
            }
            __syncthreads();
            float mx = s_bc;
            float e0 = exp_mufu(t0 - mx), e1 = exp_mufu(t1 - mx);
            float e2 = exp_mufu(t2 - mx), e3 = exp_mufu(t3 - mx);
            float s = warp_sum(e0 + e1 + e2 + e3);
            if (l == 0) red[w] = s;
            __syncthreads();
            if (tid == 0) {
                float ss = 0.0f;
#pragma unroll
                for (int i = 0; i < 8; i++) ss += red[i];
                s_bc = rcp_approx(ss);
            }
            __syncthreads();
            float inv = s_bc;
            float y0 = e0 * inv, y1 = e1 * inv, y2 = e2 * inv, y3 = e3 * inv;
            long base = (long)b * 1024 + tid * 4;
            split_w(y0, g_y_h, g_y_l, base + 0);
            split_w(y1, g_y_h, g_y_l, base + 1);
            split_w(y2, g_y_h, g_y_l, base + 2);
            split_w(y3, g_y_h, g_y_l, base + 3);
            ((float4*)(out + ((long)b * Ss + step) * Vv))[tid] =
                make_float4(y0, y1, y2, y3);
        }
        grid_barrier(NBLK);   // zeta -> next alpha
    }
}

// ---------------- launcher -------------------------------------------------------
extern "C" void kernel_launch(void* const* d_in, const int* in_sizes, int n_in,
                              void* d_out, int out_size)
{
    const float* h        = (const float*)d_in[0];
    const float* w_h_a    = (const float*)d_in[1];
    const float* w_s_a    = (const float*)d_in[2];
    const float* b_s_a    = (const float*)d_in[3];
    const float* w_a      = (const float*)d_in[4];
    const float* w_init_s = (const float*)d_in[5];
    const float* b_init_s = (const float*)d_in[6];
    const float* gru_w_ih = (const float*)d_in[7];
    const float* gru_w_hh = (const float*)d_in[8];
    const float* gru_b_ih = (const float*)d_in[9];
    const float* gru_b_hh = (const float*)d_in[10];
    const float* rnn_w_ih = (const float*)d_in[11];
    const float* rnn_w_hh = (const float*)d_in[12];
    const float* rnn_b_ih = (const float*)d_in[13];
    const float* rnn_b_hh = (const float*)d_in[14];
    float* out = (float*)d_out;

    __nv_bfloat16 *wha_h, *wha_l, *wis_h, *wis_l, *wsa_h, *wsa_l;
    __nv_bfloat16 *gwh_h, *gwh_l, *gwi_h, *gwi_l, *rwi_h, *rwi_l, *rwh_h, *rwh_l;
    __nv_bfloat16 *hh_, *hl_;
    cudaGetSymbolAddress((void**)&wha_h, g_wha_h); cudaGetSymbolAddress((void**)&wha_l, g_wha_l);
    cudaGetSymbolAddress((void**)&wis_h, g_wis_h); cudaGetSymbolAddress((void**)&wis_l, g_wis_l);
    cudaGetSymbolAddress((void**)&wsa_h, g_wsa_h); cudaGetSymbolAddress((void**)&wsa_l, g_wsa_l);
    cudaGetSymbolAddress((void**)&gwh_h, g_gwh_h); cudaGetSymbolAddress((void**)&gwh_l, g_gwh_l);
    cudaGetSymbolAddress((void**)&gwi_h, g_gwi_h); cudaGetSymbolAddress((void**)&gwi_l, g_gwi_l);
    cudaGetSymbolAddress((void**)&rwi_h, g_rwi_h); cudaGetSymbolAddress((void**)&rwi_l, g_rwi_l);
    cudaGetSymbolAddress((void**)&rwh_h, g_rwh_h); cudaGetSymbolAddress((void**)&rwh_l, g_rwh_l);
    cudaGetSymbolAddress((void**)&hh_, g_h_h);     cudaGetSymbolAddress((void**)&hl_, g_h_l);

    // prep: split-bf16 conversions
    conv_split<<<512, 256>>>(w_h_a,    wha_h, wha_l, (long)1024 * 1024);
    conv_split<<<512, 256>>>(w_init_s, wis_h, wis_l, (long)1024 * 1024);
    conv_split<<<512, 256>>>(w_s_a,    wsa_h, wsa_l, (long)1024 * 1024);
    conv_split<<<512, 256>>>(gru_w_hh, gwh_h, gwh_l, (long)3072 * 1024);
    conv_split<<<1024, 256>>>(gru_w_ih, gwi_h, gwi_l, (long)3072 * 2048);
    conv_split<<<1024, 256>>>(rnn_w_ih, rwi_h, rwi_l, (long)1024 * 2048);
    conv_split<<<512, 256>>>(rnn_w_hh, rwh_h, rwh_l, (long)1024 * 1024);
    conv_split<<<2048, 256>>>(h,       hh_,   hl_,   (long)Bb * Tt * Dd);

    // wh = h @ w_h_a^T  (tensor cores, full precision via split-bf16)
    wh_gemm_kernel<<<dim3(16, 256), 256>>>();
    // s0 partials, then state init
    s0_gemm_kernel<<<dim3(16, 4), 256>>>();
    init_state_kernel<<<512, 256>>>(b_init_s);
    // the recurrence
    persist_kernel<<<NBLK, 256>>>(h, b_s_a, w_a, gru_b_ih, gru_b_hh,
                                  rnn_b_ih, rnn_b_hh, out);
    (void)in_sizes; (void)n_in; (void)out_size;
}

// round 5
// speedup vs baseline: 1.6840x; 1.2573x over previous
#include <cuda_runtime.h>
#include <cuda_bf16.h>

#define Bb 128
#define Tt 256
#define Dd 1024
#define Hh 1024
#define Vv 1024
#define Ss 128
#define H3 3072
#define NBLK 296
#define PITCH 24   // bf16 elems per smem row: 48B, 16B-aligned

// ---------------- scratch (device globals; no cudaMalloc allowed) -----------
__device__ __align__(16) __nv_bfloat16 g_whb[(long)Bb * Tt * Hh];  // 67 MB bf16
__device__ __align__(16) float g_part_proj[8 * Bb * Hh];
__device__ __align__(16) float g_part_gi[5 * Bb * H3];   // slot0=gi_y, 1-4=gi_c
__device__ __align__(16) float g_part_gh[2 * Bb * H3];
__device__ __align__(16) float g_part_pre[13 * Bb * Vv]; // 0-3 ih_c, 4-11 ih_s, 12 hh
__device__ __align__(16) float g_s[Bb * Hh];

// split-bf16 mirrors: value = hi + lo
__device__ __align__(16) __nv_bfloat16 g_s_h[Bb * Hh], g_s_l[Bb * Hh];
__device__ __align__(16) __nv_bfloat16 g_c_h[Bb * Hh], g_c_l[Bb * Hh];
__device__ __align__(16) __nv_bfloat16 g_y_h[Bb * Hh], g_y_l[Bb * Hh];
// weights (split)
__device__ __align__(16) __nv_bfloat16 g_wsa_h[1024 * 1024], g_wsa_l[1024 * 1024];
__device__ __align__(16) __nv_bfloat16 g_gwh_h[3072 * 1024], g_gwh_l[3072 * 1024];
__device__ __align__(16) __nv_bfloat16 g_gwi_h[(long)3072 * 2048], g_gwi_l[(long)3072 * 2048];
__device__ __align__(16) __nv_bfloat16 g_rwi_h[(long)1024 * 2048], g_rwi_l[(long)1024 * 2048];
__device__ __align__(16) __nv_bfloat16 g_rwh_h[1024 * 1024], g_rwh_l[1024 * 1024];
__device__ __align__(16) __nv_bfloat16 g_wha_h[1024 * 1024], g_wha_l[1024 * 1024];
__device__ __align__(16) __nv_bfloat16 g_wis_h[1024 * 1024], g_wis_l[1024 * 1024];
__device__ __align__(16) __nv_bfloat16 g_h_h[(long)Bb * Tt * Dd], g_h_l[(long)Bb * Tt * Dd];

__device__ unsigned g_bar_count = 0;
__device__ unsigned g_bar_gen = 0;

// ---------------- math helpers -----------------------------------------------
__device__ __forceinline__ float ex2_approx(float x) {
    float r; asm("ex2.approx.ftz.f32 %0, %1;" : "=f"(r) : "f"(x)); return r;
}
__device__ __forceinline__ float rcp_approx(float x) {
    float r; asm("rcp.approx.ftz.f32 %0, %1;" : "=f"(r) : "f"(x)); return r;
}
__device__ __forceinline__ float exp_mufu(float x) {
    return ex2_approx(x * 1.4426950408889634f);
}
__device__ __forceinline__ float tanh_mufu(float x) {
    float ax = fabsf(x);
    float e  = ex2_approx(ax * -2.885390081777927f);
    float r  = rcp_approx(1.0f + e);
    float th = fmaf(-2.0f * e, r, 1.0f);
    return copysignf(th, x);
}
__device__ __forceinline__ float sigmoid_mufu(float x) {
    float e = ex2_approx(x * -1.4426950408889634f);
    return rcp_approx(1.0f + e);
}
__device__ __forceinline__ float warp_sum(float v) {
#pragma unroll
    for (int o = 16; o > 0; o >>= 1) v += __shfl_xor_sync(0xffffffffu, v, o);
    return v;
}
__device__ __forceinline__ float warp_max(float v) {
#pragma unroll
    for (int o = 16; o > 0; o >>= 1) v = fmaxf(v, __shfl_xor_sync(0xffffffffu, v, o));
    return v;
}
__device__ __forceinline__ void split_w(float v, __nv_bfloat16* hi, __nv_bfloat16* lo, long i) {
    __nv_bfloat16 hb = __float2bfloat16(v);
    hi[i] = hb;
    lo[i] = __float2bfloat16(v - __bfloat162float(hb));
}

// ---------------- grid barrier ------------------------------------------------
__device__ __forceinline__ void grid_barrier() {
    __syncthreads();
    if (threadIdx.x == 0) {
        volatile unsigned* genp = &g_bar_gen;
        unsigned gen = *genp;
        __threadfence();
        unsigned arrived = atomicAdd(&g_bar_count, 1u);
        if (arrived == NBLK - 1u) {
            *(volatile unsigned*)&g_bar_count = 0u;
            __threadfence();
            atomicExch(&g_bar_gen, gen + 1u);
        } else {
            while (*genp == gen) { }
        }
        __threadfence();
    }
    __syncthreads();
}

// ---------------- tensor-core primitives ---------------------------------------
__device__ __forceinline__ void mma16816(float* d, const unsigned* a, const unsigned* b) {
    asm volatile(
        "mma.sync.aligned.m16n8k16.row.col.f32.bf16.bf16.f32 "
        "{%0,%1,%2,%3}, {%4,%5,%6,%7}, {%8,%9}, {%0,%1,%2,%3};\n"
        : "+f"(d[0]), "+f"(d[1]), "+f"(d[2]), "+f"(d[3])
        : "r"(a[0]), "r"(a[1]), "r"(a[2]), "r"(a[3]), "r"(b[0]), "r"(b[1]));
}
__device__ __forceinline__ void ldsm4(unsigned* r, const void* p) {
    unsigned addr = (unsigned)__cvta_generic_to_shared(p);
    asm volatile("ldmatrix.sync.aligned.m8n8.x4.shared.b16 {%0,%1,%2,%3}, [%4];\n"
                 : "=r"(r[0]), "=r"(r[1]), "=r"(r[2]), "=r"(r[3]) : "r"(addr));
}

struct SmemTC {
    __nv_bfloat16 Ah[2][128][PITCH];
    __nv_bfloat16 Al[2][128][PITCH];
    __nv_bfloat16 Bh[2][64][PITCH];
    __nv_bfloat16 Bl[2][64][PITCH];
};   // 36864 B

// C[128 m][64 n] = sum_k A[m,k]*B[n,k], split-bf16 (3 MMAs), fp32 accumulate.
template<bool BF16OUT>
__device__ void gemm_tc(const __nv_bfloat16* __restrict__ Ah,
                        const __nv_bfloat16* __restrict__ Al, long lda,
                        const __nv_bfloat16* __restrict__ Bh,
                        const __nv_bfloat16* __restrict__ Bl, long ldb,
                        int kcount, void* __restrict__ Cv, int ldc, SmemTC* sm)
{
    const int tid = threadIdx.x;
    const int lane = tid & 31, wp = tid >> 5;
    const int m0 = (wp & 3) * 32, n0 = (wp >> 2) * 32;

    const int ar = tid >> 1, ac = (tid & 1) * 8;
    const int br = (tid & 127) >> 1, bc2 = (tid & 1) * 8;
    const bool blo = tid >= 128;
    const __nv_bfloat16* Bsrc = blo ? Bl : Bh;

    uint4 pah = *(const uint4*)(Ah + (long)ar * lda + ac);
    uint4 pal = *(const uint4*)(Al + (long)ar * lda + ac);
    uint4 pb  = *(const uint4*)(Bsrc + (long)br * ldb + bc2);

    float acc[2][4][4];
#pragma unroll
    for (int i = 0; i < 2; i++)
#pragma unroll
        for (int j = 0; j < 4; j++)
#pragma unroll
            for (int k = 0; k < 4; k++) acc[i][j][k] = 0.0f;

    const int arow = lane & 15;
    const int acol = (lane & 16) ? 8 : 0;
    const int brow = (lane & 7) + ((lane & 16) ? 8 : 0);
    const int bcol = (lane & 8) ? 8 : 0;

    int buf = 0;
    for (int kt = 0; kt < kcount; kt += 16) {
        *(uint4*)&sm->Ah[buf][ar][ac] = pah;
        *(uint4*)&sm->Al[buf][ar][ac] = pal;
        if (!blo) *(uint4*)&sm->Bh[buf][br][bc2] = pb;
        else      *(uint4*)&sm->Bl[buf][br][bc2] = pb;
        __syncthreads();
        if (kt + 16 < kcount) {
            pah = *(const uint4*)(Ah + (long)ar * lda + kt + 16 + ac);
            pal = *(const uint4*)(Al + (long)ar * lda + kt + 16 + ac);
            pb  = *(const uint4*)(Bsrc + (long)br * ldb + kt + 16 + bc2);
        }
        unsigned afh[2][4], afl[2][4];
#pragma unroll
        for (int mt = 0; mt < 2; mt++) {
            ldsm4(afh[mt], &sm->Ah[buf][m0 + mt * 16 + arow][acol]);
            ldsm4(afl[mt], &sm->Al[buf][m0 + mt * 16 + arow][acol]);
        }
        unsigned bfh[4][2], bfl[4][2];
#pragma unroll
        for (int hf = 0; hf < 2; hf++) {
            unsigned r[4];
            ldsm4(r, &sm->Bh[buf][n0 + hf * 16 + brow][bcol]);
            bfh[2*hf][0] = r[0]; bfh[2*hf][1] = r[1];
            bfh[2*hf+1][0] = r[2]; bfh[2*hf+1][1] = r[3];
            ldsm4(r, &sm->Bl[buf][n0 + hf * 16 + brow][bcol]);
            bfl[2*hf][0] = r[0]; bfl[2*hf][1] = r[1];
            bfl[2*hf+1][0] = r[2]; bfl[2*hf+1][1] = r[3];
        }
#pragma unroll
        for (int mt = 0; mt < 2; mt++)
#pragma unroll
            for (int nt = 0; nt < 4; nt++) {
                mma16816(acc[mt][nt], afh[mt], bfh[nt]);
                mma16816(acc[mt][nt], afh[mt], bfl[nt]);
                mma16816(acc[mt][nt], afl[mt], bfh[nt]);
            }
        buf ^= 1;
    }
    const int gr = lane >> 2, gc = (lane & 3) * 2;
#pragma unroll
    for (int mt = 0; mt < 2; mt++)
#pragma unroll
        for (int nt = 0; nt < 4; nt++) {
            long base = (long)(m0 + mt * 16 + gr) * ldc + n0 + nt * 8 + gc;
            if (BF16OUT) {
                __nv_bfloat16* C = (__nv_bfloat16*)Cv;
                *(__nv_bfloat162*)&C[base] =
                    __floats2bfloat162_rn(acc[mt][nt][0], acc[mt][nt][1]);
                *(__nv_bfloat162*)&C[base + 8 * ldc] =
                    __floats2bfloat162_rn(acc[mt][nt][2], acc[mt][nt][3]);
            } else {
                float* C = (float*)Cv;
                *(float2*)&C[base]           = make_float2(acc[mt][nt][0], acc[mt][nt][1]);
                *(float2*)&C[base + 8 * ldc] = make_float2(acc[mt][nt][2], acc[mt][nt][3]);
            }
        }
}

// ---------------- prep kernels --------------------------------------------------
__device__ void conv_seg(const float* __restrict__ x, __nv_bfloat16* __restrict__ hi,
                         __nv_bfloat16* __restrict__ lo, long n, long t0, long stride)
{
    for (long i = t0; i < n; i += stride) {
        float v = x[i];
        __nv_bfloat16 hb = __float2bfloat16(v);
        hi[i] = hb;
        lo[i] = __float2bfloat16(v - __bfloat162float(hb));
    }
}

__global__ void conv_all(const float* w_h_a, const float* w_init_s, const float* w_s_a,
                         const float* gru_w_hh, const float* gru_w_ih,
                         const float* rnn_w_ih, const float* rnn_w_hh, const float* h)
{
    long t0 = (long)blockIdx.x * blockDim.x + threadIdx.x;
    long st = (long)gridDim.x * blockDim.x;
    conv_seg(w_h_a,    g_wha_h, g_wha_l, (long)1024 * 1024, t0, st);
    conv_seg(w_init_s, g_wis_h, g_wis_l, (long)1024 * 1024, t0, st);
    conv_seg(w_s_a,    g_wsa_h, g_wsa_l, (long)1024 * 1024, t0, st);
    conv_seg(gru_w_hh, g_gwh_h, g_gwh_l, (long)3072 * 1024, t0, st);
    conv_seg(gru_w_ih, g_gwi_h, g_gwi_l, (long)3072 * 2048, t0, st);
    conv_seg(rnn_w_ih, g_rwi_h, g_rwi_l, (long)1024 * 2048, t0, st);
    conv_seg(rnn_w_hh, g_rwh_h, g_rwh_l, (long)1024 * 1024, t0, st);
    conv_seg(h,        g_h_h,   g_h_l,   (long)Bb * Tt * Dd, t0, st);
}

__global__ void __launch_bounds__(256, 2) wh_gemm_kernel()
{
    __shared__ __align__(16) SmemTC sm;
    int nt = blockIdx.x, mb = blockIdx.y;
    gemm_tc<true>(g_h_h + (long)mb * 128 * 1024, g_h_l + (long)mb * 128 * 1024, 1024,
                  g_wha_h + (long)nt * 64 * 1024, g_wha_l + (long)nt * 64 * 1024, 1024,
                  1024, g_whb + (long)mb * 128 * 1024 + nt * 64, 1024, &sm);
}

__global__ void __launch_bounds__(256, 2) s0_gemm_kernel()
{
    __shared__ __align__(16) SmemTC sm;
    int nt = blockIdx.x, z = blockIdx.y;   // 4 k-splits of 256; A rows stride T*D
    gemm_tc<false>(g_h_h + z * 256, g_h_l + z * 256, (long)Tt * Dd,
                   g_wis_h + (long)nt * 64 * 1024 + z * 256,
                   g_wis_l + (long)nt * 64 * 1024 + z * 256, 1024,
                   256, g_part_proj + z * (Bb * Hh) + nt * 64, 1024, &sm);
}

__global__ void init_state_kernel(const float* __restrict__ bias)
{
    int idx = blockIdx.x * 256 + threadIdx.x;   // < 128*1024
    int hh = idx & 1023;
    float v = bias[hh];
#pragma unroll
    for (int q = 0; q < 4; q++) v += g_part_proj[q * (Bb * Hh) + idx];
    float s = tanh_mufu(v);
    g_s[idx] = s;
    split_w(s, g_s_h, g_s_l, idx);
    g_y_h[idx] = __float2bfloat16(0.0f);
    g_y_l[idx] = __float2bfloat16(0.0f);
}

__global__ void bar_reset_kernel()
{
    if (threadIdx.x == 0) { g_bar_count = 0; g_bar_gen = 0; }
}

// ---------------- zeta: out = softmax(tanh(pre)); updates y splits --------------
__device__ void zeta_phase(int b, int step, const float* rnn_b_ih, const float* rnn_b_hh,
                           float* out, float* red, float* s_bc)
{
    const int tid = threadIdx.x;
    const int w = tid >> 5, l = tid & 31;
    float4 acc = ((const float4*)rnn_b_ih)[tid];
    float4 b2  = ((const float4*)rnn_b_hh)[tid];
    acc.x += b2.x; acc.y += b2.y; acc.z += b2.z; acc.w += b2.w;
#pragma unroll
    for (int q = 0; q < 13; q++) {
        float4 p = ((const float4*)(g_part_pre + (long)q * (Bb * Vv) + b * Vv))[tid];
        acc.x += p.x; acc.y += p.y; acc.z += p.z; acc.w += p.w;
    }
    float t0 = tanh_mufu(acc.x), t1 = tanh_mufu(acc.y);
    float t2 = tanh_mufu(acc.z), t3 = tanh_mufu(acc.w);
    float m = fmaxf(fmaxf(t0, t1), fmaxf(t2, t3));
    m = warp_max(m);
    if (l == 0) red[w] = m;
    __syncthreads();
    if (tid == 0) {
        float mm = red[0];
#pragma unroll
        for (int i = 1; i < 8; i++) mm = fmaxf(mm, red[i]);
        *s_bc = mm;
    }
    __syncthreads();
    float mx = *s_bc;
    float e0 = exp_mufu(t0 - mx), e1 = exp_mufu(t1 - mx);
    float e2 = exp_mufu(t2 - mx), e3 = exp_mufu(t3 - mx);
    float s = warp_sum(e0 + e1 + e2 + e3);
    if (l == 0) red[w] = s;
    __syncthreads();
    if (tid == 0) {
        float ss = 0.0f;
#pragma unroll
        for (int i = 0; i < 8; i++) ss += red[i];
        *s_bc = rcp_approx(ss);
    }
    __syncthreads();
    float inv = *s_bc;
    float y0 = e0 * inv, y1 = e1 * inv, y2 = e2 * inv, y3 = e3 * inv;
    long base = (long)b * 1024 + tid * 4;
    split_w(y0, g_y_h, g_y_l, base + 0);
    split_w(y1, g_y_h, g_y_l, base + 1);
    split_w(y2, g_y_h, g_y_l, base + 2);
    split_w(y3, g_y_h, g_y_l, base + 3);
    ((float4*)(out + ((long)b * Ss + step) * Vv))[tid] = make_float4(y0, y1, y2, y3);
}

// ---------------- the persistent kernel -----------------------------------------
__global__ void __launch_bounds__(256, 2)
persist_kernel(const float* __restrict__ h,
               const float* __restrict__ b_s_a, const float* __restrict__ w_a,
               const float* __restrict__ gru_b_ih, const float* __restrict__ gru_b_hh,
               const float* __restrict__ rnn_b_ih, const float* __restrict__ rnn_b_hh,
               float* __restrict__ out)
{
    __shared__ __align__(16) unsigned char sraw[sizeof(SmemTC)];
    __shared__ float s_bc;
    SmemTC* sm = (SmemTC*)sraw;
    float* p_sh = (float*)sraw;        // 1024 floats (attention)
    float* w_sh = p_sh + 1024;         // 1024
    float* sc   = w_sh + 1024;         // 256
    float* red  = sc + 256;            // 8

    const int blk = blockIdx.x;
    const int tid = threadIdx.x;
    const int w = tid >> 5, l = tid & 31;

    for (int step = 0; step < Ss; step++) {
        // ==== P1: proj (blocks 0-127) || zeta_prev (blocks 128-255)
        if (blk < 128) {                 // proj = s @ w_s_a^T : 16nt x 8z, K=128
            int nt = blk & 15, z = blk >> 4;
            gemm_tc<false>(g_s_h + z * 128, g_s_l + z * 128, 1024,
                           g_wsa_h + (long)nt * 64 * 1024 + z * 128,
                           g_wsa_l + (long)nt * 64 * 1024 + z * 128, 1024,
                           128, g_part_proj + z * (Bb * Hh) + nt * 64, Hh, sm);
        } else if (blk < 256 && step > 0) {
            zeta_phase(blk - 128, step - 1, rnn_b_ih, rnn_b_hh, out, red, &s_bc);
        }
        grid_barrier();

        // ==== P2: beta attention (0-127) || gh (128-223) || gi_y (224-271) || pre_hh (272-287)
        if (blk < 128) {
            int b = blk;
            {
                float4 acc = ((const float4*)b_s_a)[tid];
#pragma unroll
                for (int z = 0; z < 8; z++) {
                    float4 v = ((const float4*)(g_part_proj + z * (Bb * Hh) + b * Hh))[tid];
                    acc.x += v.x; acc.y += v.y; acc.z += v.z; acc.w += v.w;
                }
                ((float4*)p_sh)[tid] = acc;
                ((float4*)w_sh)[tid] = ((const float4*)w_a)[tid];
            }
            __syncthreads();
            const uint2* whb = (const uint2*)(g_whb + (long)b * Tt * Hh);
            for (int tt = 0; tt < 32; tt++) {
                int t = w * 32 + tt;
                const uint2* whp = whb + (long)t * 256;
                float acc = 0.0f;
#pragma unroll
                for (int jj = 0; jj < 8; jj++) {
                    int fi = jj * 32 + l;
                    uint2 u = whp[fi];
                    float2 f0 = __bfloat1622float2(*(__nv_bfloat162*)&u.x);
                    float2 f1 = __bfloat1622float2(*(__nv_bfloat162*)&u.y);
                    float4 p  = ((const float4*)p_sh)[fi];
                    float4 wa = ((const float4*)w_sh)[fi];
                    acc = fmaf(tanh_mufu(f0.x + p.x), wa.x, acc);
                    acc = fmaf(tanh_mufu(f0.y + p.y), wa.y, acc);
                    acc = fmaf(tanh_mufu(f1.x + p.z), wa.z, acc);
                    acc = fmaf(tanh_mufu(f1.y + p.w), wa.w, acc);
                }
                acc = warp_sum(acc);
                if (l == 0) sc[t] = acc;
            }
            __syncthreads();
            {   // softmax over sc[256]
                float v = sc[tid];
                float m = warp_max(v);
                if (l == 0) red[w] = m;
                __syncthreads();
                if (tid == 0) {
                    float mm = red[0];
#pragma unroll
                    for (int i = 1; i < 8; i++) mm = fmaxf(mm, red[i]);
                    s_bc = mm;
                }
                __syncthreads();
                float e = exp_mufu(v - s_bc);
                float s = warp_sum(e);
                if (l == 0) red[w] = s;
                __syncthreads();
                if (tid == 0) {
                    float ss = 0.0f;
#pragma unroll
                    for (int i = 0; i < 8; i++) ss += red[i];
                    s_bc = rcp_approx(ss);
                }
                __syncthreads();
                sc[tid] = e * s_bc;
            }
            __syncthreads();
            {   // ctx: c = sum_t a[t] * h[b,t,:] (fp32 h)
                const float4* hp = (const float4*)(h + (long)b * Tt * Dd);
                float4 c = make_float4(0.f, 0.f, 0.f, 0.f);
#pragma unroll 4
                for (int t = 0; t < Tt; t++) {
                    float a = sc[t];
                    float4 v = hp[(long)t * 256 + tid];
                    c.x = fmaf(a, v.x, c.x); c.y = fmaf(a, v.y, c.y);
                    c.z = fmaf(a, v.z, c.z); c.w = fmaf(a, v.w, c.w);
                }
                long base = (long)b * 1024 + tid * 4;
                split_w(c.x, g_c_h, g_c_l, base + 0);
                split_w(c.y, g_c_h, g_c_l, base + 1);
                split_w(c.z, g_c_h, g_c_l, base + 2);
                split_w(c.w, g_c_h, g_c_l, base + 3);
            }
        } else if (blk < 224) {          // gh = s @ gru_w_hh^T : 48nt x 2z, K=512
            int i = blk - 128, nt = i >> 1, z = i & 1;
            gemm_tc<false>(g_s_h + z * 512, g_s_l + z * 512, 1024,
                           g_gwh_h + (long)nt * 64 * 1024 + z * 512,
                           g_gwh_l + (long)nt * 64 * 1024 + z * 512, 1024,
                           512, g_part_gh + (long)z * (Bb * H3) + nt * 64, H3, sm);
        } else if (blk < 272) {          // gi_y = y @ Wih[:,1024:]^T : 48nt, K=1024
            int nt = blk - 224;
            gemm_tc<false>(g_y_h, g_y_l, 1024,
                           g_gwi_h + (long)nt * 64 * 2048 + 1024,
                           g_gwi_l + (long)nt * 64 * 2048 + 1024, 2048,
                           1024, g_part_gi + nt * 64, H3, sm);
        } else if (blk < 288) {          // pre_hh = y @ rnn_w_hh^T : 16nt, K=1024
            int nt = blk - 272;
            gemm_tc<false>(g_y_h, g_y_l, 1024,
                           g_rwh_h + (long)nt * 64 * 1024,
                           g_rwh_l + (long)nt * 64 * 1024, 1024,
                           1024, g_part_pre + (long)12 * (Bb * Vv) + nt * 64, Vv, sm);
        }
        grid_barrier();

        // ==== P3: gi_c (0-191) || pre_ih_c (192-255)
        if (blk < 192) {
            int nt = blk >> 2, z = blk & 3;
            gemm_tc<false>(g_c_h + z * 256, g_c_l + z * 256, 1024,
                           g_gwi_h + (long)nt * 64 * 2048 + z * 256,
                           g_gwi_l + (long)nt * 64 * 2048 + z * 256, 2048,
                           256, g_part_gi + (long)(1 + z) * (Bb * H3) + nt * 64, H3, sm);
        } else if (blk < 256) {
            int i = blk - 192, nt = i >> 2, z = i & 3;
            gemm_tc<false>(g_c_h + z * 256, g_c_l + z * 256, 1024,
                           g_rwi_h + (long)nt * 64 * 2048 + z * 256,
                           g_rwi_l + (long)nt * 64 * 2048 + z * 256, 2048,
                           256, g_part_pre + (long)z * (Bb * Vv) + nt * 64, Vv, sm);
        }
        grid_barrier();

        // ==== P4: GRU elementwise
        for (int idx = blk * 256 + tid; idx < Bb * Hh; idx += NBLK * 256) {
            int b = idx >> 10, hh = idx & 1023;
            float gir = gru_b_ih[hh], giz = gru_b_ih[1024 + hh], gin = gru_b_ih[2048 + hh];
#pragma unroll
            for (int q = 0; q < 5; q++) {
                const float* p = g_part_gi + (long)(q * Bb + b) * H3 + hh;
                gir += p[0]; giz += p[1024]; gin += p[2048];
            }
            float ghr = gru_b_hh[hh], ghz = gru_b_hh[1024 + hh], ghn = gru_b_hh[2048 + hh];
#pragma unroll
            for (int q = 0; q < 2; q++) {
                const float* p = g_part_gh + (long)(q * Bb + b) * H3 + hh;
                ghr += p[0]; ghz += p[1024]; ghn += p[2048];
            }
            float r = sigmoid_mufu(gir + ghr);
            float z = sigmoid_mufu(giz + ghz);
            float n = tanh_mufu(fmaf(r, ghn, gin));
            float sv = g_s[idx];
            float sn = fmaf(z, sv - n, n);
            g_s[idx] = sn;
            split_w(sn, g_s_h, g_s_l, idx);
        }
        grid_barrier();

        // ==== P5: pre_ih_s = s_new @ rnn_w_ih[:,1024:]^T : 16nt x 8z, K=128
        if (blk < 128) {
            int nt = blk >> 3, z = blk & 7;
            gemm_tc<false>(g_s_h + z * 128, g_s_l + z * 128, 1024,
                           g_rwi_h + (long)nt * 64 * 2048 + 1024 + z * 128,
                           g_rwi_l + (long)nt * 64 * 2048 + 1024 + z * 128, 2048,
                           128, g_part_pre + (long)(4 + z) * (Bb * Vv) + nt * 64, Vv, sm);
        }
        grid_barrier();
    }
    // tail: zeta for the final step
    if (blk < 128) {
        zeta_phase(blk, Ss - 1, rnn_b_ih, rnn_b_hh, out, red, &s_bc);
    }
}

// ---------------- launcher -------------------------------------------------------
extern "C" void kernel_launch(void* const* d_in, const int* in_sizes, int n_in,
                              void* d_out, int out_size)
{
    const float* h        = (const float*)d_in[0];
    const float* w_h_a    = (const float*)d_in[1];
    const float* w_s_a    = (const float*)d_in[2];
    const float* b_s_a    = (const float*)d_in[3];
    const float* w_a      = (const float*)d_in[4];
    const float* w_init_s = (const float*)d_in[5];
    const float* b_init_s = (const float*)d_in[6];
    const float* gru_w_ih = (const float*)d_in[7];
    const float* gru_w_hh = (const float*)d_in[8];
    const float* gru_b_ih = (const float*)d_in[9];
    const float* gru_b_hh = (const float*)d_in[10];
    const float* rnn_w_ih = (const float*)d_in[11];
    const float* rnn_w_hh = (const float*)d_in[12];
    const float* rnn_b_ih = (const float*)d_in[13];
    const float* rnn_b_hh = (const float*)d_in[14];
    float* out = (float*)d_out;

    // launch 1: all split-bf16 conversions
    conv_all<<<2048, 256>>>(w_h_a, w_init_s, w_s_a, gru_w_hh, gru_w_ih,
                            rnn_w_ih, rnn_w_hh, h);
    // launch 2: wh = h @ w_h_a^T -> bf16
    wh_gemm_kernel<<<dim3(16, 256), 256>>>();
    // launch 3: s0 partials
    s0_gemm_kernel<<<dim3(16, 4), 256>>>();
    // launch 4: state init
    init_state_kernel<<<512, 256>>>(b_init_s);
    // launch 5: barrier reset (also makes persist the 6th launch for ncu -s 5)
    bar_reset_kernel<<<1, 32>>>();
    // launch 6: the recurrence
    persist_kernel<<<NBLK, 256>>>(h, b_s_a, w_a, gru_b_ih, gru_b_hh,
                                  rnn_b_ih, rnn_b_hh, out);
    (void)in_sizes; (void)n_in; (void)out_size;
}